// round 3
// baseline (speedup 1.0000x reference)
#include <cuda_runtime.h>
#include <math.h>

#define NLEVELS 16
#define TBL (1 << 18)          // T = 2^18 entries per level
#define PI2 2654435761u
#define THREADS 256
#define GRID_CTAS 608          // persistent: 4 CTAs x 152 SMs (GB300)
#define SMEM_LEVELS 3          // levels 0..2 cached in shared memory

struct Params {
    int ns[NLEVELS];
};

__global__ __launch_bounds__(THREADS, 4)
void hash_enc_kernel(const float2* __restrict__ xy,
                     const float2* __restrict__ tables,   // (L, T) of float2
                     float* __restrict__ out,
                     int B,
                     Params P)
{
    extern __shared__ float2 sm[];

    // ---- cooperative fill of levels 0..2 into shared memory ----
    const int sz0 = (P.ns[0] + 1) * (P.ns[0] + 1);
    const int sz1 = (P.ns[1] + 1) * (P.ns[1] + 1);
    const int sz2 = (P.ns[2] + 1) * (P.ns[2] + 1);
    const int off1 = sz0;
    const int off2 = sz0 + sz1;
    const int total = sz0 + sz1 + sz2;

    for (int j = threadIdx.x; j < total; j += THREADS) {
        int l, base;
        if (j < off1)      { l = 0; base = 0;    }
        else if (j < off2) { l = 1; base = off1; }
        else               { l = 2; base = off2; }
        sm[j] = tables[(size_t)l * TBL + (j - base)];
    }
    __syncthreads();

    const int smoff[SMEM_LEVELS] = {0, off1, off2};

    // ---- persistent grid-stride loop over points ----
    for (int i = blockIdx.x * THREADS + threadIdx.x; i < B;
         i += GRID_CTAS * THREADS) {

        float2 q = xy[i];
        float x = fminf(fmaxf(q.x, 0.0f), 1.0f);
        float y = fminf(fmaxf(q.y, 0.0f), 1.0f);

        float res[2 * NLEVELS];

        #pragma unroll
        for (int l = 0; l < NLEVELS; ++l) {
            const int Nl = P.ns[l];
            const float Nf = (float)Nl;

            float px = x * Nf;
            float py = y * Nf;
            float fx0 = floorf(px);
            float fy0 = floorf(py);
            float wx = px - fx0;
            float wy = py - fy0;

            int x0 = (int)fx0;
            int y0 = (int)fy0;
            int x1 = min(x0 + 1, Nl);
            int y1 = min(y0 + 1, Nl);

            float2 f00, f10, f01, f11;

            if (l < SMEM_LEVELS) {
                // dense, table resident in shared memory
                unsigned stride = (unsigned)(Nl + 1);
                const float2* t = sm + smoff[l];
                f00 = t[(unsigned)x0 * stride + (unsigned)y0];
                f10 = t[(unsigned)x1 * stride + (unsigned)y0];
                f01 = t[(unsigned)x0 * stride + (unsigned)y1];
                f11 = t[(unsigned)x1 * stride + (unsigned)y1];
            } else if (l <= 5) {
                // dense, global.  (Nl+1)^2 <= 2^18 holds for levels 0..5:
                // NS = 16,29,53,97,177,322 (<=511) vs 588+ for level 6+.
                unsigned stride = (unsigned)(Nl + 1);
                const float2* tab = tables + (size_t)l * TBL;
                f00 = __ldg(tab + (unsigned)x0 * stride + (unsigned)y0);
                f10 = __ldg(tab + (unsigned)x1 * stride + (unsigned)y0);
                f01 = __ldg(tab + (unsigned)x0 * stride + (unsigned)y1);
                f11 = __ldg(tab + (unsigned)x1 * stride + (unsigned)y1);
            } else {
                // hashed: (xi ^ (yi * PI2)) mod T.  T = 2^18 divides 2^32, so
                // uint32 wraparound is congruent to the reference's int64 math.
                unsigned hy0 = (unsigned)y0 * PI2;
                unsigned hy1 = (unsigned)y1 * PI2;
                const float2* tab = tables + (size_t)l * TBL;
                f00 = __ldg(tab + (((unsigned)x0 ^ hy0) & (TBL - 1)));
                f10 = __ldg(tab + (((unsigned)x1 ^ hy0) & (TBL - 1)));
                f01 = __ldg(tab + (((unsigned)x0 ^ hy1) & (TBL - 1)));
                f11 = __ldg(tab + (((unsigned)x1 ^ hy1) & (TBL - 1)));
            }

            float w00 = (1.0f - wx) * (1.0f - wy);
            float w10 = wx * (1.0f - wy);
            float w01 = (1.0f - wx) * wy;
            float w11 = wx * wy;

            res[2 * l]     = f00.x * w00 + f10.x * w10 + f01.x * w01 + f11.x * w11;
            res[2 * l + 1] = f00.y * w00 + f10.y * w10 + f01.y * w01 + f11.y * w11;
        }

        float4* o = (float4*)(out + (size_t)i * (2 * NLEVELS));
        #pragma unroll
        for (int k = 0; k < 8; ++k) {
            o[k] = make_float4(res[4*k], res[4*k+1], res[4*k+2], res[4*k+3]);
        }
    }
}

extern "C" void kernel_launch(void* const* d_in, const int* in_sizes, int n_in,
                              void* d_out, int out_size)
{
    const float2* xy     = (const float2*)d_in[0];
    const float2* tables = (const float2*)d_in[1];
    float* out           = (float*)d_out;

    int B = in_sizes[0] / 2;

    // Replicate the reference's NS computation with identical double-precision
    // libm calls so floor() decisions match bit-for-bit.
    Params P;
    double b = exp((log(131072.0) - log(16.0)) / 15.0);
    for (int l = 0; l < NLEVELS; ++l) {
        P.ns[l] = (int)floor(16.0 * pow(b, (double)l));
    }

    // shared memory for levels 0..2 (float2 entries)
    size_t smem = 0;
    for (int l = 0; l < SMEM_LEVELS; ++l) {
        smem += (size_t)(P.ns[l] + 1) * (P.ns[l] + 1) * sizeof(float2);
    }

    hash_enc_kernel<<<GRID_CTAS, THREADS, smem>>>(xy, tables, out, B, P);
}

// round 4
// speedup vs baseline: 1.1620x; 1.1620x over previous
#include <cuda_runtime.h>
#include <math.h>

#define NLEVELS 16
#define TBL (1 << 18)          // T = 2^18 entries per level
#define PI2 2654435761u
#define THREADS 256

#define BPTS (1 << 21)         // B = 2^21 points
#define MBITS 9                // Morton bits per dim
#define NBINS (1 << (2 * MBITS))   // 262144 bins
#define SCAN_CTAS 256          // NBINS / 1024

struct Params {
    int ns[NLEVELS];
};

// ---- static scratch (no allocations allowed) ----
__device__ float2   g_xy[BPTS];        // permuted points
__device__ int      g_idx[BPTS];       // original index of permuted point
__device__ unsigned g_hist[NBINS];     // histogram, then per-bin cursor
__device__ unsigned g_bsum[SCAN_CTAS]; // per-block totals for scan

// ---------------------------------------------------------------------------
__device__ __forceinline__ unsigned expand_bits(unsigned v) {
    // 9 -> 18 bit interleave expansion
    v &= 0x1FF;
    v = (v | (v << 8)) & 0x00FF00FFu;
    v = (v | (v << 4)) & 0x0F0F0F0Fu;
    v = (v | (v << 2)) & 0x33333333u;
    v = (v | (v << 1)) & 0x55555555u;
    return v;
}

__device__ __forceinline__ unsigned morton_bin(float2 q) {
    float x = fminf(fmaxf(q.x, 0.0f), 1.0f);
    float y = fminf(fmaxf(q.y, 0.0f), 1.0f);
    unsigned xb = min((unsigned)(x * 512.0f), 511u);
    unsigned yb = min((unsigned)(y * 512.0f), 511u);
    return (expand_bits(xb) << 1) | expand_bits(yb);
}

// ---- K0: zero histogram ----
__global__ void k_zero() {
    int i = blockIdx.x * blockDim.x + threadIdx.x;
    if (i < NBINS) g_hist[i] = 0;
}

// ---- K1: histogram ----
__global__ void k_hist(const float2* __restrict__ xy, int B) {
    int i = blockIdx.x * blockDim.x + threadIdx.x;
    if (i < B) atomicAdd(&g_hist[morton_bin(xy[i])], 1u);
}

// ---- K2: per-block exclusive scan (1024 bins per CTA) ----
__global__ __launch_bounds__(1024)
void k_scan1() {
    __shared__ unsigned sh[1024];
    int base = blockIdx.x * 1024;
    unsigned v = g_hist[base + threadIdx.x];
    sh[threadIdx.x] = v;
    __syncthreads();
    // Hillis-Steele inclusive scan
    #pragma unroll
    for (int off = 1; off < 1024; off <<= 1) {
        unsigned t = (threadIdx.x >= off) ? sh[threadIdx.x - off] : 0;
        __syncthreads();
        sh[threadIdx.x] += t;
        __syncthreads();
    }
    // exclusive = inclusive - self
    g_hist[base + threadIdx.x] = sh[threadIdx.x] - v;
    if (threadIdx.x == 1023) g_bsum[blockIdx.x] = sh[1023];
}

// ---- K3: scan block totals (single CTA) ----
__global__ __launch_bounds__(SCAN_CTAS)
void k_scan2() {
    __shared__ unsigned sh[SCAN_CTAS];
    unsigned v = g_bsum[threadIdx.x];
    sh[threadIdx.x] = v;
    __syncthreads();
    #pragma unroll
    for (int off = 1; off < SCAN_CTAS; off <<= 1) {
        unsigned t = (threadIdx.x >= off) ? sh[threadIdx.x - off] : 0;
        __syncthreads();
        sh[threadIdx.x] += t;
        __syncthreads();
    }
    g_bsum[threadIdx.x] = sh[threadIdx.x] - v;   // exclusive
}

// ---- K4: add block offsets -> g_hist holds per-bin start cursors ----
__global__ __launch_bounds__(1024)
void k_scan3() {
    int i = blockIdx.x * 1024 + threadIdx.x;
    g_hist[i] += g_bsum[blockIdx.x];
}

// ---- K5: scatter points into bin order ----
__global__ void k_scatter(const float2* __restrict__ xy, int B) {
    int i = blockIdx.x * blockDim.x + threadIdx.x;
    if (i >= B) return;
    float2 q = xy[i];
    unsigned p = atomicAdd(&g_hist[morton_bin(q)], 1u);
    g_xy[p]  = q;
    g_idx[p] = i;
}

// ---- K6: main encode kernel (reads permuted points) ----
__global__ __launch_bounds__(THREADS)
void hash_enc_kernel(float* __restrict__ out,
                     const float2* __restrict__ tables,
                     int B, Params P)
{
    int i = blockIdx.x * THREADS + threadIdx.x;
    if (i >= B) return;

    float2 q = g_xy[i];
    int oidx  = g_idx[i];
    float x = fminf(fmaxf(q.x, 0.0f), 1.0f);
    float y = fminf(fmaxf(q.y, 0.0f), 1.0f);

    float res[2 * NLEVELS];

    #pragma unroll
    for (int l = 0; l < NLEVELS; ++l) {
        const int Nl = P.ns[l];
        const float Nf = (float)Nl;

        float px = x * Nf;
        float py = y * Nf;
        float fx0 = floorf(px);
        float fy0 = floorf(py);
        float wx = px - fx0;
        float wy = py - fy0;

        int x0 = (int)fx0;
        int y0 = (int)fy0;
        int x1 = min(x0 + 1, Nl);
        int y1 = min(y0 + 1, Nl);

        unsigned i00, i10, i01, i11;
        // Dense iff (Nl+1)^2 <= 2^18 <=> Nl <= 511  (levels 0..5).
        if (Nl <= 511) {
            unsigned stride = (unsigned)(Nl + 1);
            i00 = (unsigned)x0 * stride + (unsigned)y0;
            i10 = (unsigned)x1 * stride + (unsigned)y0;
            i01 = (unsigned)x0 * stride + (unsigned)y1;
            i11 = (unsigned)x1 * stride + (unsigned)y1;
        } else {
            // hashed: (xi ^ (yi*PI2)) mod 2^18; uint32 math is congruent
            // to the reference's int64 math since 2^18 | 2^32.
            unsigned hy0 = (unsigned)y0 * PI2;
            unsigned hy1 = (unsigned)y1 * PI2;
            i00 = ((unsigned)x0 ^ hy0) & (TBL - 1);
            i10 = ((unsigned)x1 ^ hy0) & (TBL - 1);
            i01 = ((unsigned)x0 ^ hy1) & (TBL - 1);
            i11 = ((unsigned)x1 ^ hy1) & (TBL - 1);
        }

        const float2* tab = tables + (size_t)l * TBL;
        float2 f00 = __ldg(tab + i00);
        float2 f10 = __ldg(tab + i10);
        float2 f01 = __ldg(tab + i01);
        float2 f11 = __ldg(tab + i11);

        float w00 = (1.0f - wx) * (1.0f - wy);
        float w10 = wx * (1.0f - wy);
        float w01 = (1.0f - wx) * wy;
        float w11 = wx * wy;

        res[2 * l]     = f00.x * w00 + f10.x * w10 + f01.x * w01 + f11.x * w11;
        res[2 * l + 1] = f00.y * w00 + f10.y * w10 + f01.y * w01 + f11.y * w11;
    }

    float4* o = (float4*)(out + (size_t)oidx * (2 * NLEVELS));
    #pragma unroll
    for (int k = 0; k < 8; ++k) {
        o[k] = make_float4(res[4*k], res[4*k+1], res[4*k+2], res[4*k+3]);
    }
}

// ---------------------------------------------------------------------------
extern "C" void kernel_launch(void* const* d_in, const int* in_sizes, int n_in,
                              void* d_out, int out_size)
{
    const float2* xy     = (const float2*)d_in[0];
    const float2* tables = (const float2*)d_in[1];
    float* out           = (float*)d_out;

    int B = in_sizes[0] / 2;

    // Replicate the reference's NS computation with identical double-precision
    // libm calls so floor() decisions match bit-for-bit.
    Params P;
    double b = exp((log(131072.0) - log(16.0)) / 15.0);
    for (int l = 0; l < NLEVELS; ++l) {
        P.ns[l] = (int)floor(16.0 * pow(b, (double)l));
    }

    int pblocks = (B + THREADS - 1) / THREADS;

    k_zero   <<<(NBINS + 255) / 256, 256>>>();
    k_hist   <<<pblocks, THREADS>>>(xy, B);
    k_scan1  <<<SCAN_CTAS, 1024>>>();
    k_scan2  <<<1, SCAN_CTAS>>>();
    k_scan3  <<<SCAN_CTAS, 1024>>>();
    k_scatter<<<pblocks, THREADS>>>(xy, B);
    hash_enc_kernel<<<pblocks, THREADS>>>(out, tables, B, P);
}